// round 12
// baseline (speedup 1.0000x reference)
#include <cuda_runtime.h>

#define S 2048
#define DM 512
#define NI 13
#define NC 117

typedef unsigned long long ull;

// ---------------- scratch ----------------
__device__ float  g_Wp[DM * 128];            // padded W, [k][128]
__device__ float4 g_plin[NI * S];            // {x0, y0, cw, sw} lin channel, [i][a]
__device__ float4 g_pang[NI * S];            // ang channel
__device__ float2 g_slin[64 * NI * S];       // boundary states lin: [m][i][a], b0=32m
__device__ float2 g_sang[64 * NI * S];       // boundary states ang
__device__ float  g_base[NI * S];            // min + noise_bias, [i][b]
__device__ float  g_partial[16 * NI * S];    // [ca][i][b]
__device__ int    g_cnt[NI * 16];            // per-(i,cb) counters (self-resetting)

// ---------------- packed f32x2 helpers ----------------
__device__ __forceinline__ ull pk2(float lo, float hi) {
    ull r; asm("mov.b64 %0, {%1,%2};" : "=l"(r) : "f"(lo), "f"(hi)); return r;
}
__device__ __forceinline__ void upk2(ull v, float& lo, float& hi) {
    asm("mov.b64 {%0,%1}, %2;" : "=f"(lo), "=f"(hi) : "l"(v));
}
__device__ __forceinline__ ull fma2(ull a, ull b, ull c) {
    ull d; asm("fma.rn.f32x2 %0, %1, %2, %3;" : "=l"(d) : "l"(a), "l"(b), "l"(c)); return d;
}
__device__ __forceinline__ ull mul2(ull a, ull b) {
    ull d; asm("mul.rn.f32x2 %0, %1, %2;" : "=l"(d) : "l"(a), "l"(b)); return d;
}
__device__ __forceinline__ ull add2(ull a, ull b) {
    ull d; asm("add.rn.f32x2 %0, %1, %2;" : "=l"(d) : "l"(a), "l"(b)); return d;
}
__device__ __forceinline__ ull neg2(ull a) { return a ^ 0x8000000080000000ULL; }

__device__ __forceinline__ float softplus_f(float x) {
    return fmaxf(x, 0.0f) + log1pf(expf(-fabsf(x)));
}

// ---------------- 0) pad W (float4 stores) + zero counters ----------------
__global__ void wprep_kernel(const float* __restrict__ W) {
    int idx4 = blockIdx.x * 256 + threadIdx.x;   // DM*128/4 = 16384
    int k  = idx4 >> 5;
    int c0 = (idx4 & 31) * 4;
    const float* Wr = W + k * NC;
    float4 v;
    v.x = (c0 + 0 < NC) ? Wr[c0 + 0] : 0.0f;
    v.y = (c0 + 1 < NC) ? Wr[c0 + 1] : 0.0f;
    v.z = (c0 + 2 < NC) ? Wr[c0 + 2] : 0.0f;
    v.w = (c0 + 3 < NC) ? Wr[c0 + 3] : 0.0f;
    ((float4*)g_Wp)[idx4] = v;
    if (idx4 < NI * 16) g_cnt[idx4] = 0;
}

// ---------------- 1) fused LN + GEMM(split-K) + transform + state table ----
// 128 blocks x 256 threads. Block = 16 tokens.
#define XROW 18
__global__ __launch_bounds__(256) void gemm_fused(
    const float* __restrict__ h, const float* __restrict__ mn,
    const float* __restrict__ lw, const float* __restrict__ lb,
    const float* __restrict__ bias)
{
    __shared__ __align__(16) float xsT[DM * XROW];   // 36.9 KB; reused as ps4 later

    int t  = threadIdx.x;
    int s0 = blockIdx.x * 16;

    // ---- LayerNorm: 16 threads per row, 16 rows; store TRANSPOSED ----
    {
        int r = t >> 4, sub = t & 15;
        const float4* h4 = (const float4*)h;
        float4 v[8];
        float sum = 0.f, sq = 0.f;
        #pragma unroll
        for (int q = 0; q < 8; q++) {
            v[q] = h4[(s0 + r) * (DM / 4) + sub + q * 16];
            sum += v[q].x + v[q].y + v[q].z + v[q].w;
            sq  += v[q].x * v[q].x + v[q].y * v[q].y + v[q].z * v[q].z + v[q].w * v[q].w;
        }
        #pragma unroll
        for (int o = 8; o; o >>= 1) {
            sum += __shfl_xor_sync(0xffffffffu, sum, o);
            sq  += __shfl_xor_sync(0xffffffffu, sq,  o);
        }
        float mu   = sum * (1.0f / DM);
        float var  = sq * (1.0f / DM) - mu * mu;
        float rstd = rsqrtf(var + 1e-5f);
        const float4* lw4 = (const float4*)lw;
        const float4* lb4 = (const float4*)lb;
        #pragma unroll
        for (int q = 0; q < 8; q++) {
            float4 wv = lw4[sub + q * 16], bv = lb4[sub + q * 16];
            int k0 = (sub + q * 16) * 4;
            xsT[(k0 + 0) * XROW + r] = (v[q].x - mu) * rstd * wv.x + bv.x;
            xsT[(k0 + 1) * XROW + r] = (v[q].y - mu) * rstd * wv.y + bv.y;
            xsT[(k0 + 2) * XROW + r] = (v[q].z - mu) * rstd * wv.z + bv.z;
            xsT[(k0 + 3) * XROW + r] = (v[q].w - mu) * rstd * wv.w + bv.w;
        }
    }
    __syncthreads();

    // ---- GEMM: warp = 8 tokens (4 pairs) x 128 cols, over its K quarter ----
    int lane = t & 31, w = t >> 5;
    int tokg = (w & 1) * 8, kq = w >> 1;
    ull A[4][4];
    #pragma unroll
    for (int p = 0; p < 4; p++)
        #pragma unroll
        for (int q = 0; q < 4; q++) A[p][q] = 0ULL;

    const float4* Wp4 = (const float4*)g_Wp;
    int kbeg = kq * 128, kend = kbeg + 128;
    #pragma unroll 8
    for (int k = kbeg; k < kend; k++) {
        ull x01 = *(const ull*)&xsT[k * XROW + tokg + 0];
        ull x23 = *(const ull*)&xsT[k * XROW + tokg + 2];
        ull x45 = *(const ull*)&xsT[k * XROW + tokg + 4];
        ull x67 = *(const ull*)&xsT[k * XROW + tokg + 6];
        float4 wv = Wp4[k * 32 + lane];
        ull wd0 = pk2(wv.x, wv.x), wd1 = pk2(wv.y, wv.y);
        ull wd2 = pk2(wv.z, wv.z), wd3 = pk2(wv.w, wv.w);
        A[0][0] = fma2(x01, wd0, A[0][0]); A[0][1] = fma2(x01, wd1, A[0][1]);
        A[0][2] = fma2(x01, wd2, A[0][2]); A[0][3] = fma2(x01, wd3, A[0][3]);
        A[1][0] = fma2(x23, wd0, A[1][0]); A[1][1] = fma2(x23, wd1, A[1][1]);
        A[1][2] = fma2(x23, wd2, A[1][2]); A[1][3] = fma2(x23, wd3, A[1][3]);
        A[2][0] = fma2(x45, wd0, A[2][0]); A[2][1] = fma2(x45, wd1, A[2][1]);
        A[2][2] = fma2(x45, wd2, A[2][2]); A[2][3] = fma2(x45, wd3, A[2][3]);
        A[3][0] = fma2(x67, wd0, A[3][0]); A[3][1] = fma2(x67, wd1, A[3][1]);
        A[3][2] = fma2(x67, wd2, A[3][2]); A[3][3] = fma2(x67, wd3, A[3][3]);
    }
    __syncthreads();   // x no longer needed; reuse xsT as ps4[4][16][128]

    // ---- write per-quarter partials (c = 4*lane + q) ----
    float* ps4 = xsT;
    #pragma unroll
    for (int p = 0; p < 4; p++) {
        #pragma unroll
        for (int q = 0; q < 4; q++) {
            float e0, e1; upk2(A[p][q], e0, e1);
            int c = 4 * lane + q;
            int tok0 = tokg + 2 * p;
            ps4[(kq * 16 + tok0) * 128 + c]     = e0;
            ps4[(kq * 16 + tok0 + 1) * 128 + c] = e1;
        }
    }
    __syncthreads();

    // ---- sum 4 quarters into quarter 0 (ps[tok][c]) ----
    {
        float4* q0 = (float4*)ps4;
        #pragma unroll
        for (int j = 0; j < 2; j++) {
            int u4 = t * 2 + j;                 // 512 float4 slots = 16x128
            float4 a = q0[u4];
            float4 b = q0[512 + u4];
            float4 c = q0[1024 + u4];
            float4 d = q0[1536 + u4];
            a.x += b.x + c.x + d.x;
            a.y += b.y + c.y + d.y;
            a.z += b.z + c.z + d.z;
            a.w += b.w + c.w + d.w;
            q0[u4] = a;
        }
    }
    __syncthreads();

    // ---- transform + boundary-state table: 16 tok x 13 i x 2 ch = 416 units --
    float* ps = ps4;
    for (int u = t; u < 16 * NI * 2; u += 256) {
        int r   = u / (2 * NI);
        int rem = u - r * 2 * NI;
        int i = rem >> 1, ch = rem & 1;
        int s = s0 + r;
        const float* P = ps + r * 128;
        int ck  = (ch ? 2 : 0) * NI + i;
        int cd  = (ch ? 3 : 1) * NI + i;
        int cc  = (ch ? 5 : 4) * NI + i;
        int cph = (ch ? 7 : 6) * NI + i;
        float pk  = P[ck]  + bias[ck];
        float pd  = P[cd]  + bias[cd];
        float pc  = P[cc]  + bias[cc];
        float pph = P[cph] + bias[cph];

        float d  = sqrtf(pd * pd + 1e-5f);
        float sp = softplus_f(pk);
        float kk = d * d * 0.25f + sp;
        float om = 0.5f * sqrtf(fmaxf(4.0f * kk - d * d, 0.0f));
        float dec = expf(-0.5f * d);
        float so, co; sincosf(om, &so, &co);
        float sph, cph_; sincosf(pph, &sph, &cph_);
        float x0 = pc * cph_, y0 = pc * sph;
        float cw = dec * co,  sw = dec * so;
        if (ch) g_pang[i * S + s] = make_float4(x0, y0, cw, sw);
        else {
            g_plin[i * S + s] = make_float4(x0, y0, cw, sw);
            int c8 = 8 * NI + i;
            g_base[i * S + s] = mn[0] + P[c8] + bias[c8];
        }

        // ---- boundary states: b0 = 32m for m in [mfirst, 64) ----
        int mfirst = ((s >> 7) + 1) * 4;
        if (mfirst < 64) {
            // w^32: 5 squarings
            float c32 = cw, s32 = sw;
            #pragma unroll
            for (int q2 = 0; q2 < 5; q2++) {
                float cn = c32 * c32 - s32 * s32;
                s32 = 2.0f * c32 * s32;
                c32 = cn;
            }
            // w^e0, e0 = 32*mfirst - s in [1,128]: 8-iter branchless binexp
            unsigned e = (unsigned)(32 * mfirst - s);
            float rx = 1.0f, ry = 0.0f, bx = cw, by = sw;
            #pragma unroll
            for (int it = 0; it < 8; it++) {
                float tx = rx * bx - ry * by;
                float ty = rx * by + ry * bx;
                bool mm = (e & 1u) != 0u;
                rx = mm ? tx : rx;
                ry = mm ? ty : ry;
                e >>= 1;
                float cn = bx * bx - by * by;
                by = 2.0f * bx * by;
                bx = cn;
            }
            float sx = x0 * rx - y0 * ry;
            float sy = x0 * ry + y0 * rx;
            float2* tab = ch ? g_sang : g_slin;
            for (int m = mfirst; m < 64; m++) {
                tab[(m * NI + i) * S + s] = make_float2(sx, sy);
                float nx = sx * c32 - sy * s32;
                sy = sx * s32 + sy * c32;
                sx = nx;
            }
        }
    }
}

// ---------------- 2) triangular sweep + fused final fold ----------------
// smem: ull buffer 32 b-slots x stride 33 = 8448 B.
// Store: sbuf[bb*33 + lane]  imm-offset STS.64, bank (bb+lane)&31, conflict-free.
// Fold:  lane reads row lane: sbuf[lane*33 + c], bank (lane+c)&31, conflict-free.

__device__ __forceinline__ void fold32(const ull* sbuf, float* pout, int lane) {
    const ull* row = sbuf + lane * 33;
    ull a0 = 0ULL, a1 = 0ULL, a2 = 0ULL, a3 = 0ULL;
    #pragma unroll
    for (int c = 0; c < 32; c += 4) {
        a0 = add2(a0, row[c + 0]);
        a1 = add2(a1, row[c + 1]);
        a2 = add2(a2, row[c + 2]);
        a3 = add2(a3, row[c + 3]);
    }
    ull acc = add2(add2(a0, a1), add2(a2, a3));
    float lo, hi; upk2(acc, lo, hi);
    pout[lane] = lo + hi;
}

// full quarter: 128 a's (4 groups), 32 b-steps; init from boundary table (no cpow)
__device__ __forceinline__ void run_full_q(int a0, int m, int i, float* pout,
                                           int lane, ull* sbuf) {
    ull X[4], Y[4], CW[4], SW[4], CW2[4], SW2[4], NSW2[4];
    #pragma unroll
    for (int j = 0; j < 4; j++) {
        int a = a0 + j * 32 + lane;
        float4 pl = g_plin[i * S + a];
        float4 pa = g_pang[i * S + a];
        float2 sl = g_slin[(m * NI + i) * S + a];
        float2 sa = g_sang[(m * NI + i) * S + a];
        CW[j] = pk2(pl.z, pa.z);
        SW[j] = pk2(pl.w, pa.w);
        ull t2 = mul2(CW[j], SW[j]);
        CW2[j]  = fma2(CW[j], CW[j], neg2(mul2(SW[j], SW[j])));
        SW2[j]  = add2(t2, t2);
        NSW2[j] = neg2(SW2[j]);
        X[j] = pk2(sl.x, sa.x);
        Y[j] = pk2(sl.y, sa.y);
    }
    #pragma unroll
    for (int it = 0; it < 16; it++) {
        int bb0 = it * 2;
        sbuf[bb0 * 33 + lane] = add2(add2(Y[0], Y[1]), add2(Y[2], Y[3]));
        ull sB = add2(add2(fma2(X[0], SW[0], mul2(Y[0], CW[0])),
                           fma2(X[1], SW[1], mul2(Y[1], CW[1]))),
                      add2(fma2(X[2], SW[2], mul2(Y[2], CW[2])),
                           fma2(X[3], SW[3], mul2(Y[3], CW[3]))));
        sbuf[(bb0 + 1) * 33 + lane] = sB;
        #pragma unroll
        for (int j = 0; j < 4; j++) {
            ull t1 = mul2(Y[j], NSW2[j]);
            ull t2 = mul2(X[j], SW2[j]);
            X[j] = fma2(X[j], CW2[j], t1);
            Y[j] = fma2(Y[j], CW2[j], t2);
        }
    }
    __syncwarp();
    fold32(sbuf, pout, lane);
}

// diagonal tile: 128 a's (4 groups), 128 single steps with birth predicate
__device__ __forceinline__ void run_diag(int b0, int i, float* pout,
                                         int lane, ull* sbuf) {
    ull X[4], Y[4], CW[4], SW[4], NSW[4], X0[4], Y0[4];
    int aj[4];
    #pragma unroll
    for (int j = 0; j < 4; j++) {
        int a = b0 + j * 32 + lane;
        aj[j] = a;
        float4 pl = g_plin[i * S + a];
        float4 pa = g_pang[i * S + a];
        CW[j]  = pk2(pl.z, pa.z);
        SW[j]  = pk2(pl.w, pa.w);
        NSW[j] = neg2(SW[j]);
        X0[j] = pk2(pl.x, pa.x);
        Y0[j] = pk2(pl.y, pa.y);
        X[j] = 0ULL; Y[j] = 0ULL;
    }
    #pragma unroll 1
    for (int chunk = 0; chunk < 4; chunk++) {
        #pragma unroll
        for (int bb = 0; bb < 32; bb++) {
            int b = b0 + chunk * 32 + bb;
            #pragma unroll
            for (int j = 0; j < 4; j++) {
                bool hit = (b == aj[j]);
                X[j] = hit ? X0[j] : X[j];
                Y[j] = hit ? Y0[j] : Y[j];
            }
            sbuf[bb * 33 + lane] = add2(add2(Y[0], Y[1]), add2(Y[2], Y[3]));
            #pragma unroll
            for (int j = 0; j < 4; j++) {
                ull t1 = mul2(Y[j], NSW[j]);
                ull t2 = mul2(X[j], SW[j]);
                X[j] = fma2(X[j], CW[j], t1);
                Y[j] = fma2(Y[j], CW[j], t2);
            }
        }
        __syncwarp();
        fold32(sbuf, pout + chunk * 32, lane);
        __syncwarp();
    }
}

// grid (496, 13): slots 0..15 diag (cb = slot); slots 16..495: full quarters:
//   f = slot-16; per cb group size 4*cb; ca = f>>2, q = f&3; b0 = cb*128+q*32.
// Last finisher of (i, cb) column (4cb+1 tiles) folds base+partials -> out.
__global__ __launch_bounds__(32) void sweep_kernel(float* __restrict__ out) {
    __shared__ ull sbuf[32 * 33];   // 8448 B
    int slot = blockIdx.x, i = blockIdx.y;
    int lane = threadIdx.x;
    int cb;
    if (slot < 16) {
        cb = slot;
        float* pout = g_partial + (cb * NI + i) * S + cb * 128;
        run_diag(cb * 128, i, pout, lane, sbuf);
    } else {
        int f = slot - 16;
        cb = 1;
        while (f >= 4 * cb) { f -= 4 * cb; cb++; }
        int ca = f >> 2, q = f & 3;
        int m = cb * 4 + q;
        float* pout = g_partial + (ca * NI + i) * S + m * 32;
        run_full_q(ca * 128, m, i, pout, lane, sbuf);
    }

    // fused fold: last tile of (i, cb) column writes the output
    __threadfence();
    int last = 0;
    if (lane == 0)
        last = (atomicAdd(&g_cnt[i * 16 + cb], 1) == 4 * cb);
    last = __shfl_sync(0xffffffffu, last, 0);
    if (last) {
        __threadfence();
        #pragma unroll
        for (int g = 0; g < 4; g++) {
            int b = cb * 128 + g * 32 + lane;
            float acc = g_base[i * S + b];
            #pragma unroll
            for (int c2 = 0; c2 < 16; c2++)
                if (c2 <= cb) acc += g_partial[(c2 * NI + i) * S + b];
            out[i * S + b] = acc;
        }
        if (lane == 0) g_cnt[i * 16 + cb] = 0;   // self-reset for next replay
    }
}

// ---------------- launch ----------------
extern "C" void kernel_launch(void* const* d_in, const int* in_sizes, int n_in,
                              void* d_out, int out_size) {
    const float* h    = (const float*)d_in[0];
    const float* mn   = (const float*)d_in[1];
    const float* lw   = (const float*)d_in[2];
    const float* lb   = (const float*)d_in[3];
    const float* W    = (const float*)d_in[4];
    const float* bias = (const float*)d_in[5];
    float* out = (float*)d_out;

    wprep_kernel<<<64, 256>>>(W);
    gemm_fused<<<S / 16, 256>>>(h, mn, lw, lb, bias);
    dim3 g(496, NI);
    sweep_kernel<<<g, 32>>>(out);
}

// round 13
// speedup vs baseline: 1.4829x; 1.4829x over previous
#include <cuda_runtime.h>

#define S 2048
#define DM 512
#define NI 13
#define NC 117

typedef unsigned long long ull;

// ---------------- scratch ----------------
__device__ float  g_Wp[DM * 128];            // padded W, [k][128]; cols>=117 stay 0
__device__ float4 g_plin[NI * S];            // {x0, y0, cw, sw} lin channel, [i][a]
__device__ float4 g_pang[NI * S];            // ang channel
__device__ float  g_base[NI * S];            // min + noise_bias, [i][b]
__device__ float  g_partial[16 * NI * S];    // [ca][i][b]
__device__ int    g_cnt[NI * 16];            // per-(i,cb) counters (self-resetting)

// ---------------- packed f32x2 helpers ----------------
__device__ __forceinline__ ull pk2(float lo, float hi) {
    ull r; asm("mov.b64 %0, {%1,%2};" : "=l"(r) : "f"(lo), "f"(hi)); return r;
}
__device__ __forceinline__ void upk2(ull v, float& lo, float& hi) {
    asm("mov.b64 {%0,%1}, %2;" : "=f"(lo), "=f"(hi) : "l"(v));
}
__device__ __forceinline__ ull fma2(ull a, ull b, ull c) {
    ull d; asm("fma.rn.f32x2 %0, %1, %2, %3;" : "=l"(d) : "l"(a), "l"(b), "l"(c)); return d;
}
__device__ __forceinline__ ull mul2(ull a, ull b) {
    ull d; asm("mul.rn.f32x2 %0, %1, %2;" : "=l"(d) : "l"(a), "l"(b)); return d;
}
__device__ __forceinline__ ull add2(ull a, ull b) {
    ull d; asm("add.rn.f32x2 %0, %1, %2;" : "=l"(d) : "l"(a), "l"(b)); return d;
}
__device__ __forceinline__ ull neg2(ull a) { return a ^ 0x8000000080000000ULL; }

__device__ __forceinline__ float softplus_f(float x) {
    return fmaxf(x, 0.0f) + log1pf(expf(-fabsf(x)));
}

// branchless packed complex pow: (rx,ry) = (bx,by)^e, e < 2048
__device__ __forceinline__ void cpow2(ull bx, ull by, unsigned e, ull& rx, ull& ry) {
    rx = pk2(1.0f, 1.0f); ry = pk2(0.0f, 0.0f);
    #pragma unroll
    for (int it = 0; it < 11; it++) {
        ull tx = fma2(rx, bx, neg2(mul2(ry, by)));
        ull ty = fma2(rx, by, mul2(ry, bx));
        bool m = (e & 1u) != 0u;
        rx = m ? tx : rx;
        ry = m ? ty : ry;
        e >>= 1;
        ull t2 = mul2(bx, by);
        bx = fma2(bx, bx, neg2(mul2(by, by)));
        by = add2(t2, t2);
    }
}

// ---------------- 1) fused LN + GEMM(split-K) + param transform ----------------
// 128 blocks x 256 threads. Block = 16 tokens.
#define XROW 18
__global__ __launch_bounds__(256) void gemm_fused(
    const float* __restrict__ h, const float* __restrict__ mn,
    const float* __restrict__ lw, const float* __restrict__ lb,
    const float* __restrict__ bias)
{
    __shared__ __align__(16) float xsT[DM * XROW];   // 36.9 KB; reused as ps4 later

    int t  = threadIdx.x;
    int s0 = blockIdx.x * 16;

    // ---- LayerNorm: 16 threads per row, 16 rows; store TRANSPOSED ----
    {
        int r = t >> 4, sub = t & 15;
        const float4* h4 = (const float4*)h;
        float4 v[8];
        float sum = 0.f, sq = 0.f;
        #pragma unroll
        for (int q = 0; q < 8; q++) {
            v[q] = h4[(s0 + r) * (DM / 4) + sub + q * 16];
            sum += v[q].x + v[q].y + v[q].z + v[q].w;
            sq  += v[q].x * v[q].x + v[q].y * v[q].y + v[q].z * v[q].z + v[q].w * v[q].w;
        }
        #pragma unroll
        for (int o = 8; o; o >>= 1) {
            sum += __shfl_xor_sync(0xffffffffu, sum, o);
            sq  += __shfl_xor_sync(0xffffffffu, sq,  o);
        }
        float mu   = sum * (1.0f / DM);
        float var  = sq * (1.0f / DM) - mu * mu;
        float rstd = rsqrtf(var + 1e-5f);
        const float4* lw4 = (const float4*)lw;
        const float4* lb4 = (const float4*)lb;
        #pragma unroll
        for (int q = 0; q < 8; q++) {
            float4 wv = lw4[sub + q * 16], bv = lb4[sub + q * 16];
            int k0 = (sub + q * 16) * 4;
            xsT[(k0 + 0) * XROW + r] = (v[q].x - mu) * rstd * wv.x + bv.x;
            xsT[(k0 + 1) * XROW + r] = (v[q].y - mu) * rstd * wv.y + bv.y;
            xsT[(k0 + 2) * XROW + r] = (v[q].z - mu) * rstd * wv.z + bv.z;
            xsT[(k0 + 3) * XROW + r] = (v[q].w - mu) * rstd * wv.w + bv.w;
        }
    }
    __syncthreads();

    // ---- GEMM: warp = 8 tokens (4 pairs) x 128 cols, over its K quarter ----
    int lane = t & 31, w = t >> 5;
    int tokg = (w & 1) * 8, kq = w >> 1;
    ull A[4][4];
    #pragma unroll
    for (int p = 0; p < 4; p++)
        #pragma unroll
        for (int q = 0; q < 4; q++) A[p][q] = 0ULL;

    const float4* Wp4 = (const float4*)g_Wp;
    int kbeg = kq * 128, kend = kbeg + 128;
    #pragma unroll 8
    for (int k = kbeg; k < kend; k++) {
        ull x01 = *(const ull*)&xsT[k * XROW + tokg + 0];
        ull x23 = *(const ull*)&xsT[k * XROW + tokg + 2];
        ull x45 = *(const ull*)&xsT[k * XROW + tokg + 4];
        ull x67 = *(const ull*)&xsT[k * XROW + tokg + 6];
        float4 wv = Wp4[k * 32 + lane];
        ull wd0 = pk2(wv.x, wv.x), wd1 = pk2(wv.y, wv.y);
        ull wd2 = pk2(wv.z, wv.z), wd3 = pk2(wv.w, wv.w);
        A[0][0] = fma2(x01, wd0, A[0][0]); A[0][1] = fma2(x01, wd1, A[0][1]);
        A[0][2] = fma2(x01, wd2, A[0][2]); A[0][3] = fma2(x01, wd3, A[0][3]);
        A[1][0] = fma2(x23, wd0, A[1][0]); A[1][1] = fma2(x23, wd1, A[1][1]);
        A[1][2] = fma2(x23, wd2, A[1][2]); A[1][3] = fma2(x23, wd3, A[1][3]);
        A[2][0] = fma2(x45, wd0, A[2][0]); A[2][1] = fma2(x45, wd1, A[2][1]);
        A[2][2] = fma2(x45, wd2, A[2][2]); A[2][3] = fma2(x45, wd3, A[2][3]);
        A[3][0] = fma2(x67, wd0, A[3][0]); A[3][1] = fma2(x67, wd1, A[3][1]);
        A[3][2] = fma2(x67, wd2, A[3][2]); A[3][3] = fma2(x67, wd3, A[3][3]);
    }
    __syncthreads();   // x no longer needed; reuse xsT as ps4[4][16][128]

    // ---- write per-quarter partials (c = 4*lane + q) ----
    float* ps4 = xsT;
    #pragma unroll
    for (int p = 0; p < 4; p++) {
        #pragma unroll
        for (int q = 0; q < 4; q++) {
            float e0, e1; upk2(A[p][q], e0, e1);
            int c = 4 * lane + q;
            int tok0 = tokg + 2 * p;
            ps4[(kq * 16 + tok0) * 128 + c]     = e0;
            ps4[(kq * 16 + tok0 + 1) * 128 + c] = e1;
        }
    }
    __syncthreads();

    // ---- sum 4 quarters into quarter 0 (ps[tok][c]) ----
    {
        float4* q0 = (float4*)ps4;
        #pragma unroll
        for (int j = 0; j < 2; j++) {
            int u4 = t * 2 + j;                 // 512 float4 slots = 16x128
            float4 a = q0[u4];
            float4 b = q0[512 + u4];
            float4 c = q0[1024 + u4];
            float4 d = q0[1536 + u4];
            a.x += b.x + c.x + d.x;
            a.y += b.y + c.y + d.y;
            a.z += b.z + c.z + d.z;
            a.w += b.w + c.w + d.w;
            q0[u4] = a;
        }
    }
    __syncthreads();

    // ---- param transform: 16 tokens x 13 imus x 2 channels = 416 units ----
    float* ps = ps4;
    for (int u = t; u < 16 * NI * 2; u += 256) {
        int r   = u / (2 * NI);
        int rem = u - r * 2 * NI;
        int i = rem >> 1, ch = rem & 1;
        int s = s0 + r;
        const float* P = ps + r * 128;
        int ck  = (ch ? 2 : 0) * NI + i;
        int cd  = (ch ? 3 : 1) * NI + i;
        int cc  = (ch ? 5 : 4) * NI + i;
        int cph = (ch ? 7 : 6) * NI + i;
        float pk  = P[ck]  + bias[ck];
        float pd  = P[cd]  + bias[cd];
        float pc  = P[cc]  + bias[cc];
        float pph = P[cph] + bias[cph];

        float d  = sqrtf(pd * pd + 1e-5f);
        float sp = softplus_f(pk);
        float kk = d * d * 0.25f + sp;
        float om = 0.5f * sqrtf(fmaxf(4.0f * kk - d * d, 0.0f));
        float dec = expf(-0.5f * d);
        float so, co; sincosf(om, &so, &co);
        float sph, cph_; sincosf(pph, &sph, &cph_);
        float4 v = make_float4(pc * cph_, pc * sph, dec * co, dec * so);
        if (ch) g_pang[i * S + s] = v;
        else {
            g_plin[i * S + s] = v;
            int c8 = 8 * NI + i;
            g_base[i * S + s] = mn[0] + P[c8] + bias[c8];
        }
    }
}

// ---------------- 2) triangular sweep + fused final fold ----------------
// smem: ull buffer 32 b-slots x stride 33 = 8448 B.
// Store: sbuf[bb*33 + lane]  imm-offset STS.64, bank (bb+lane)&31, conflict-free.
// Fold:  lane reads row lane: sbuf[lane*33 + c], bank (lane+c)&31, conflict-free.

__device__ __forceinline__ void fold32(const ull* sbuf, float* pout, int lane) {
    const ull* row = sbuf + lane * 33;
    ull a0 = 0ULL, a1 = 0ULL, a2 = 0ULL, a3 = 0ULL;
    #pragma unroll
    for (int c = 0; c < 32; c += 4) {
        a0 = add2(a0, row[c + 0]);
        a1 = add2(a1, row[c + 1]);
        a2 = add2(a2, row[c + 2]);
        a3 = add2(a3, row[c + 3]);
    }
    ull acc = add2(add2(a0, a1), add2(a2, a3));
    float lo, hi; upk2(acc, lo, hi);
    pout[lane] = lo + hi;
}

// steady tile: 128 a's, 128 b's, double-step (emit b, b+1; rotate by w^2)
__device__ __forceinline__ void run_full(int a0, int b0, int i, float* pout,
                                         int lane, ull* sbuf) {
    ull X[4], Y[4], CW[4], SW[4], CW2[4], SW2[4], NSW2[4];
    #pragma unroll
    for (int j = 0; j < 4; j++) {
        int a = a0 + j * 32 + lane;
        float4 pl = g_plin[i * S + a];
        float4 pa = g_pang[i * S + a];
        CW[j] = pk2(pl.z, pa.z);
        SW[j] = pk2(pl.w, pa.w);
        ull t2 = mul2(CW[j], SW[j]);
        CW2[j]  = fma2(CW[j], CW[j], neg2(mul2(SW[j], SW[j])));
        SW2[j]  = add2(t2, t2);
        NSW2[j] = neg2(SW2[j]);
        ull rx, ry;
        cpow2(CW[j], SW[j], (unsigned)(b0 - a), rx, ry);
        ull x0 = pk2(pl.x, pa.x), y0 = pk2(pl.y, pa.y);
        X[j] = fma2(x0, rx, neg2(mul2(y0, ry)));
        Y[j] = fma2(x0, ry, mul2(y0, rx));
    }
    #pragma unroll 1
    for (int chunk = 0; chunk < 4; chunk++) {
        #pragma unroll
        for (int it = 0; it < 16; it++) {
            int bb0 = it * 2;
            sbuf[bb0 * 33 + lane] = add2(add2(Y[0], Y[1]), add2(Y[2], Y[3]));
            ull sB = add2(add2(fma2(X[0], SW[0], mul2(Y[0], CW[0])),
                               fma2(X[1], SW[1], mul2(Y[1], CW[1]))),
                          add2(fma2(X[2], SW[2], mul2(Y[2], CW[2])),
                               fma2(X[3], SW[3], mul2(Y[3], CW[3]))));
            sbuf[(bb0 + 1) * 33 + lane] = sB;
            #pragma unroll
            for (int j = 0; j < 4; j++) {
                ull t1 = mul2(Y[j], NSW2[j]);
                ull t2b = mul2(X[j], SW2[j]);
                X[j] = fma2(X[j], CW2[j], t1);
                Y[j] = fma2(Y[j], CW2[j], t2b);
            }
        }
        __syncwarp();
        fold32(sbuf, pout + chunk * 32, lane);
        __syncwarp();
    }
}

// diagonal tile: 128 a's, 128 single steps with birth predicate
__device__ __forceinline__ void run_diag(int b0, int i, float* pout,
                                         int lane, ull* sbuf) {
    ull X[4], Y[4], CW[4], SW[4], NSW[4], X0[4], Y0[4];
    int aj[4];
    #pragma unroll
    for (int j = 0; j < 4; j++) {
        int a = b0 + j * 32 + lane;
        aj[j] = a;
        float4 pl = g_plin[i * S + a];
        float4 pa = g_pang[i * S + a];
        CW[j]  = pk2(pl.z, pa.z);
        SW[j]  = pk2(pl.w, pa.w);
        NSW[j] = neg2(SW[j]);
        X0[j] = pk2(pl.x, pa.x);
        Y0[j] = pk2(pl.y, pa.y);
        X[j] = 0ULL; Y[j] = 0ULL;
    }
    #pragma unroll 1
    for (int chunk = 0; chunk < 4; chunk++) {
        #pragma unroll
        for (int bb = 0; bb < 32; bb++) {
            int b = b0 + chunk * 32 + bb;
            #pragma unroll
            for (int j = 0; j < 4; j++) {
                bool hit = (b == aj[j]);
                X[j] = hit ? X0[j] : X[j];
                Y[j] = hit ? Y0[j] : Y[j];
            }
            sbuf[bb * 33 + lane] = add2(add2(Y[0], Y[1]), add2(Y[2], Y[3]));
            #pragma unroll
            for (int j = 0; j < 4; j++) {
                ull t1 = mul2(Y[j], NSW[j]);
                ull t2 = mul2(X[j], SW[j]);
                X[j] = fma2(X[j], CW[j], t1);
                Y[j] = fma2(Y[j], CW[j], t2);
            }
        }
        __syncwarp();
        fold32(sbuf, pout + chunk * 32, lane);
        __syncwarp();
    }
}

// grid (136, 13): slot -> (ca, cb) triangular, ca <= cb. Last tile of a
// (i, cb) column (cb+1 tiles) folds base + partials -> out, resets counter.
__global__ __launch_bounds__(32) void sweep_kernel(float* __restrict__ out) {
    __shared__ ull sbuf[32 * 33];   // 8448 B
    int slot = blockIdx.x, i = blockIdx.y;
    int lane = threadIdx.x;
    int s = slot, cb = 0;
    while (s > cb) { s -= (cb + 1); cb++; }
    int ca = s;
    float* pout = g_partial + (ca * NI + i) * S + cb * 128;
    if (ca == cb) run_diag(cb * 128, i, pout, lane, sbuf);
    else          run_full(ca * 128, cb * 128, i, pout, lane, sbuf);

    // fused fold: last tile of (i, cb) column writes the output
    __threadfence();
    int last = 0;
    if (lane == 0)
        last = (atomicAdd(&g_cnt[i * 16 + cb], 1) == cb);
    last = __shfl_sync(0xffffffffu, last, 0);
    if (last) {
        __threadfence();
        #pragma unroll
        for (int g = 0; g < 4; g++) {
            int b = cb * 128 + g * 32 + lane;
            float acc = g_base[i * S + b];
            #pragma unroll
            for (int c2 = 0; c2 < 16; c2++)
                if (c2 <= cb) acc += g_partial[(c2 * NI + i) * S + b];
            out[i * S + b] = acc;
        }
        if (lane == 0) g_cnt[i * 16 + cb] = 0;   // self-reset for next replay
    }
}

// ---------------- launch ----------------
extern "C" void kernel_launch(void* const* d_in, const int* in_sizes, int n_in,
                              void* d_out, int out_size) {
    const float* h    = (const float*)d_in[0];
    const float* mn   = (const float*)d_in[1];
    const float* lw   = (const float*)d_in[2];
    const float* lb   = (const float*)d_in[3];
    const float* W    = (const float*)d_in[4];
    const float* bias = (const float*)d_in[5];
    float* out = (float*)d_out;

    // pad W via DMA: [512][117] -> [512][128] (cols 117..127 statically zero)
    void* wp_ptr = nullptr;
    cudaGetSymbolAddress(&wp_ptr, g_Wp);
    cudaMemcpy2DAsync(wp_ptr, 128 * sizeof(float),
                      W, NC * sizeof(float),
                      NC * sizeof(float), DM,
                      cudaMemcpyDeviceToDevice);

    gemm_fused<<<S / 16, 256>>>(h, mn, lw, lb, bias);
    dim3 g(136, NI);
    sweep_kernel<<<g, 32>>>(out);
}